// round 9
// baseline (speedup 1.0000x reference)
#include <cuda_runtime.h>
#include <math.h>

#define BSZ 2
#define SSZ 2048
#define DSZ 1024
#define HN  16
#define DK  64
#define NPAIR 32

__device__ float g_Q[BSZ*HN*SSZ*DK];
__device__ float g_K[BSZ*HN*SSZ*DK];
__device__ float g_V[BSZ*HN*SSZ*DK];
__device__ float g_O[BSZ*SSZ*DSZ];
__device__ float g_X[BSZ*SSZ*DSZ];     // tf32-rounded x
__device__ float g_Wq[DSZ*DSZ];        // tf32-rounded weights
__device__ float g_Wk[DSZ*DSZ];
__device__ float g_Wv[DSZ*DSZ];
__device__ float g_Wo[DSZ*DSZ];
__device__ float g_cos[SSZ*NPAIR];
__device__ float g_sin[SSZ*NPAIR];

// ---------------------------------------------------------------------------
// helpers
// ---------------------------------------------------------------------------
__device__ __forceinline__ unsigned f2tf(float f) {
    unsigned u;
    asm("cvt.rna.tf32.f32 %0, %1;" : "=r"(u) : "f"(f));
    return u;
}
__device__ __forceinline__ float f2tff(float f) { return __uint_as_float(f2tf(f)); }

__device__ __forceinline__ float ex2(float x) {
    float y;
    asm("ex2.approx.f32 %0, %1;" : "=f"(y) : "f"(x));
    return y;
}

__device__ __forceinline__ void mma8(float* c, const unsigned* a, const unsigned* b) {
    asm volatile(
        "mma.sync.aligned.m16n8k8.row.col.f32.tf32.tf32.f32 "
        "{%0,%1,%2,%3}, {%4,%5,%6,%7}, {%8,%9}, {%0,%1,%2,%3};"
        : "+f"(c[0]), "+f"(c[1]), "+f"(c[2]), "+f"(c[3])
        : "r"(a[0]), "r"(a[1]), "r"(a[2]), "r"(a[3]), "r"(b[0]), "r"(b[1]));
}

__device__ __forceinline__ void cpa16(float* s, const float* g) {
    unsigned sa = (unsigned)__cvta_generic_to_shared(s);
    asm volatile("cp.async.cg.shared.global [%0], [%1], 16;" :: "r"(sa), "l"(g));
}
__device__ __forceinline__ void cpa_commit() {
    asm volatile("cp.async.commit_group;");
}
template <int N>
__device__ __forceinline__ void cpa_wait() {
    asm volatile("cp.async.wait_group %0;" :: "n"(N));
}

// ---------------------------------------------------------------------------
// Merged tf32 pre-round pass: x + 4 weight matrices in one launch
// ---------------------------------------------------------------------------
#define NX4 (BSZ*SSZ*DSZ/4)
#define NW4 (DSZ*DSZ/4)

__global__ void tf32_round_all_kernel(const float4* __restrict__ x,
                                      const float4* __restrict__ wq,
                                      const float4* __restrict__ wk,
                                      const float4* __restrict__ wv,
                                      const float4* __restrict__ wo) {
    int i = blockIdx.x * blockDim.x + threadIdx.x;
    const float4* src;
    float4* dst;
    if (i < NX4) {
        src = x + i;
        dst = (float4*)g_X + i;
    } else {
        int j = i - NX4;
        int wsel = j / NW4;
        int off = j - wsel * NW4;
        src = (wsel == 0 ? wq : wsel == 1 ? wk : wsel == 2 ? wv : wo) + off;
        dst = (float4*)(wsel == 0 ? g_Wq : wsel == 1 ? g_Wk : wsel == 2 ? g_Wv : g_Wo) + off;
    }
    float4 v = *src;
    float4 o;
    o.x = f2tff(v.x); o.y = f2tff(v.y); o.z = f2tff(v.z); o.w = f2tff(v.w);
    *dst = o;
}

// ---------------------------------------------------------------------------
// RoPE table
// ---------------------------------------------------------------------------
__global__ void rope_table_kernel() {
    int i = blockIdx.x * blockDim.x + threadIdx.x;
    if (i >= SSZ * NPAIR) return;
    int s = i >> 5, p = i & 31;
    double ang = (double)s * exp(-(double)p * (9.210340371976184 / 32.0));
    g_cos[i] = (float)cos(ang);
    g_sin[i] = (float)sin(ang);
}

// ---------------------------------------------------------------------------
// tf32 NT-GEMM (unchanged from R7): C[128x128] = A[128x1024] * W[128x1024]^T
// 128 thr / 4 warps in 2x2, warp tile 64x64, BK=32, 3-stage cp.async,
// fragment double-buffer across the 4 k-steps in a stage.
// ---------------------------------------------------------------------------
#define GST 36
#define GSTG 3
#define GBUF (128*GST)
#define NKT 32

struct GemmCtx { int g, t, wm, wn; };

__device__ __forceinline__ void gemm_issue(
    float* As, float* Bs, int st,
    const float* __restrict__ A, const float* __restrict__ W,
    int m0, int n0, int kb)
{
    float* as = As + st * GBUF;
    float* bs = Bs + st * GBUF;
    const int r0 = threadIdx.x >> 3;
    const int c4 = (threadIdx.x & 7) << 2;
#pragma unroll
    for (int i = 0; i < 8; i++) {
        int r = r0 + 16 * i;
        cpa16(&as[r * GST + c4], A + (size_t)(m0 + r) * 1024 + kb + c4);
        cpa16(&bs[r * GST + c4], W + (size_t)(n0 + r) * 1024 + kb + c4);
    }
}

__device__ __forceinline__ void gemm_ldfrag(
    const float* as, const float* bs, int ks,
    unsigned (&af)[4][4], unsigned (&bf)[8][2], const GemmCtx& cx)
{
    const int k0 = ks * 8;
#pragma unroll
    for (int mt = 0; mt < 4; mt++) {
        const float* p = as + (cx.wm + mt*16 + cx.g) * GST + k0 + cx.t;
        af[mt][0] = __float_as_uint(p[0]);
        af[mt][1] = __float_as_uint(p[8*GST]);
        af[mt][2] = __float_as_uint(p[4]);
        af[mt][3] = __float_as_uint(p[8*GST + 4]);
    }
#pragma unroll
    for (int nt = 0; nt < 8; nt++) {
        const float* p = bs + (cx.wn + nt*8 + cx.g) * GST + k0 + cx.t;
        bf[nt][0] = __float_as_uint(p[0]);
        bf[nt][1] = __float_as_uint(p[4]);
    }
}

__device__ __forceinline__ void gemm_main(
    const float* __restrict__ A, const float* __restrict__ W,
    int m0, int n0, float (&acc)[4][8][4],
    float* As, float* Bs, const GemmCtx& cx)
{
#pragma unroll
    for (int s = 0; s < GSTG - 1; s++) {
        gemm_issue(As, Bs, s, A, W, m0, n0, s * 32);
        cpa_commit();
    }
    unsigned af[2][4][4], bf[2][8][2];
    for (int kb = 0; kb < NKT; kb++) {
        cpa_wait<GSTG - 2>();
        __syncthreads();
        if (kb + GSTG - 1 < NKT)
            gemm_issue(As, Bs, (kb + GSTG - 1) % GSTG, A, W, m0, n0, (kb + GSTG - 1) * 32);
        cpa_commit();

        const float* as = As + (kb % GSTG) * GBUF;
        const float* bs = Bs + (kb % GSTG) * GBUF;
        gemm_ldfrag(as, bs, 0, af[0], bf[0], cx);
#pragma unroll
        for (int ks = 0; ks < 4; ks++) {
            const int cur = ks & 1;
            if (ks < 3)
                gemm_ldfrag(as, bs, ks + 1, af[cur ^ 1], bf[cur ^ 1], cx);
#pragma unroll
            for (int nt = 0; nt < 8; nt++)
#pragma unroll
                for (int mt = 0; mt < 4; mt++)
                    mma8(acc[mt][nt], af[cur][mt], bf[cur][nt]);
        }
    }
}

// QKV projection with fused RoPE, scattered to [B,H,S,dk], tf32-rounded output
__global__ __launch_bounds__(128) void gemm_qkv_kernel()
{
    extern __shared__ float sm[];
    float* As = sm;
    float* Bs = sm + GSTG * GBUF;

    const int z = blockIdx.z;
    const float* W = z == 0 ? g_Wq : (z == 1 ? g_Wk : g_Wv);
    float* dst     = z == 0 ? g_Q  : (z == 1 ? g_K  : g_V);

    const int lane = threadIdx.x & 31;
    const int wid = threadIdx.x >> 5;
    GemmCtx cx;
    cx.g = lane >> 2; cx.t = lane & 3;
    cx.wm = (wid & 1) * 64; cx.wn = (wid >> 1) * 64;
    const int m0 = blockIdx.y * 128, n0 = blockIdx.x * 128;

    float acc[4][8][4];
#pragma unroll
    for (int i = 0; i < 4; i++)
#pragma unroll
        for (int j = 0; j < 8; j++)
#pragma unroll
            for (int k = 0; k < 4; k++) acc[i][j][k] = 0.f;

    gemm_main(g_X, W, m0, n0, acc, As, Bs, cx);

    const bool do_rope = (z < 2);
#pragma unroll
    for (int mt = 0; mt < 4; mt++) {
        int m = m0 + cx.wm + mt * 16 + cx.g;
        int b = m >> 11, s = m & (SSZ - 1);
#pragma unroll
        for (int nt = 0; nt < 8; nt++) {
            int n = n0 + cx.wn + nt * 8 + 2 * cx.t;
            int h = n >> 6, c = n & 63;
            float v0 = acc[mt][nt][0], v1 = acc[mt][nt][1];
            float v2 = acc[mt][nt][2], v3 = acc[mt][nt][3];
            if (do_rope) {
                int p = c >> 1;
                float ca0 = g_cos[(s << 5) | p],       sa0 = g_sin[(s << 5) | p];
                float ca1 = g_cos[((s + 8) << 5) | p], sa1 = g_sin[((s + 8) << 5) | p];
                float r0 = v0 * ca0 - v1 * sa0;
                float r1 = v0 * sa0 + v1 * ca0;
                float r2 = v2 * ca1 - v3 * sa1;
                float r3 = v2 * sa1 + v3 * ca1;
                v0 = r0; v1 = r1; v2 = r2; v3 = r3;
            }
            v0 = f2tff(v0); v1 = f2tff(v1); v2 = f2tff(v2); v3 = f2tff(v3);
            float* base = dst + (((size_t)b * HN + h) * SSZ) * DK + c;
            *(float2*)(base + (size_t)s * DK)       = make_float2(v0, v1);
            *(float2*)(base + (size_t)(s + 8) * DK) = make_float2(v2, v3);
        }
    }
}

// Output projection: out = g_O @ g_Wo^T (both pre-rounded)
__global__ __launch_bounds__(128) void gemm_out_kernel(float* __restrict__ C)
{
    extern __shared__ float sm[];
    float* As = sm;
    float* Bs = sm + GSTG * GBUF;

    const int lane = threadIdx.x & 31;
    const int wid = threadIdx.x >> 5;
    GemmCtx cx;
    cx.g = lane >> 2; cx.t = lane & 3;
    cx.wm = (wid & 1) * 64; cx.wn = (wid >> 1) * 64;
    const int m0 = blockIdx.y * 128, n0 = blockIdx.x * 128;

    float acc[4][8][4];
#pragma unroll
    for (int i = 0; i < 4; i++)
#pragma unroll
        for (int j = 0; j < 8; j++)
#pragma unroll
            for (int k = 0; k < 4; k++) acc[i][j][k] = 0.f;

    gemm_main(g_O, g_Wo, m0, n0, acc, As, Bs, cx);

#pragma unroll
    for (int mt = 0; mt < 4; mt++) {
        int m = m0 + cx.wm + mt * 16 + cx.g;
#pragma unroll
        for (int nt = 0; nt < 8; nt++) {
            int n = n0 + cx.wn + nt * 8 + 2 * cx.t;
            *(float2*)(C + (size_t)m * 1024 + n)       = make_float2(acc[mt][nt][0], acc[mt][nt][1]);
            *(float2*)(C + (size_t)(m + 8) * 1024 + n) = make_float2(acc[mt][nt][2], acc[mt][nt][3]);
        }
    }
}

// ---------------------------------------------------------------------------
// tf32 flash attention: 256 thr / 8 warps, BQ=128, BK=64, dk=64.
// Warp w owns q rows w*16..w*16+15 (ONE m-tile -> ~160 regs, 16 warps/SM).
// exp2-domain softmax. smem: sQP[128][76], sK[2][64][68], sV[2][64][72].
// ---------------------------------------------------------------------------
#define SQ_ST 76
#define SK_ST 68
#define SV_ST 72
#define SK_BUF (64*SK_ST)
#define SV_BUF (64*SV_ST)

__global__ __launch_bounds__(256) void attn_kernel() {
    extern __shared__ float sm[];
    float* sQP = sm;                               // 128*76
    float* sK0 = sm + 128*SQ_ST;                   // 2 x 64*68
    float* sV0 = sm + 128*SQ_ST + 2*SK_BUF;        // 2 x 64*72

    const int tid = threadIdx.x;
    const int w = tid >> 5;
    const int lane = tid & 31;
    const int g = lane >> 2, t = lane & 3;
    const int qb = (int)gridDim.x - 1 - (int)blockIdx.x;   // heavy CTAs first
    const int bh = blockIdx.y;
    const float* Qg = g_Q + (size_t)bh * SSZ * DK;
    const float* Kg = g_K + (size_t)bh * SSZ * DK;
    const float* Vg = g_V + (size_t)bh * SSZ * DK;
    const int kb_max = 2 * qb + 1;

    // prologue: issue K/V block 0 loads (64x64 each, 256 thr)
#pragma unroll
    for (int i = 0; i < 4; i++) {
        int e = i * 256 + tid;
        int r = e >> 4, c = (e & 15) << 2;
        cpa16(&sK0[r * SK_ST + c], &Kg[(size_t)r * DK + c]);
        cpa16(&sV0[r * SV_ST + c], &Vg[(size_t)r * DK + c]);
    }
    cpa_commit();

    // stage Q: scale by (1/sqrt(dk)) * log2(e), round to tf32
    const float qscale = 0.125f * 1.4426950408889634f;
#pragma unroll
    for (int i = 0; i < 8; i++) {
        int e = i * 256 + tid;
        int r = e >> 4, c = (e & 15) << 2;
        float4 v = *(const float4*)&Qg[(size_t)(qb * 128 + r) * DK + c];
        float4 o;
        o.x = f2tff(v.x * qscale); o.y = f2tff(v.y * qscale);
        o.z = f2tff(v.z * qscale); o.w = f2tff(v.w * qscale);
        *(float4*)&sQP[r * SQ_ST + c] = o;
    }
    __syncthreads();

    // hoist Q fragments: 8 k-steps x 4 regs (warp tile = 16 q rows)
    const int qr = w * 16 + g;
    unsigned qf[8][4];
#pragma unroll
    for (int ks = 0; ks < 8; ks++) {
        const float* p = &sQP[qr * SQ_ST + ks * 8 + t];
        qf[ks][0] = __float_as_uint(p[0]);
        qf[ks][1] = __float_as_uint(p[8 * SQ_ST]);
        qf[ks][2] = __float_as_uint(p[4]);
        qf[ks][3] = __float_as_uint(p[8 * SQ_ST + 4]);
    }

    float mrun[2] = {-1e30f, -1e30f};
    float lrun[2] = {0.f, 0.f};
    float oacc[8][4];
#pragma unroll
    for (int nt = 0; nt < 8; nt++)
#pragma unroll
        for (int k = 0; k < 4; k++) oacc[nt][k] = 0.f;

    for (int kb = 0; kb <= kb_max; kb++) {
        __syncthreads();   // buffer (kb+1)&1 free; Q->qf hoist done (kb=0)
        if (kb < kb_max) {
            float* sK = sK0 + ((kb + 1) & 1) * SK_BUF;
            float* sV = sV0 + ((kb + 1) & 1) * SV_BUF;
#pragma unroll
            for (int i = 0; i < 4; i++) {
                int e = i * 256 + tid;
                int r = e >> 4, c = (e & 15) << 2;
                cpa16(&sK[r * SK_ST + c], &Kg[(size_t)((kb + 1) * 64 + r) * DK + c]);
                cpa16(&sV[r * SV_ST + c], &Vg[(size_t)((kb + 1) * 64 + r) * DK + c]);
            }
        }
        cpa_commit();
        cpa_wait<1>();
        __syncthreads();

        const float* sK = sK0 + (kb & 1) * SK_BUF;
        const float* sV = sV0 + (kb & 1) * SV_BUF;

        // S = Q K^T : 16x64 warp tile, 8 n-tiles x 8 k-steps
        float s[8][4];
#pragma unroll
        for (int nt = 0; nt < 8; nt++)
#pragma unroll
            for (int k = 0; k < 4; k++) s[nt][k] = 0.f;

#pragma unroll
        for (int ks = 0; ks < 8; ks++) {
            unsigned kf[8][2];
#pragma unroll
            for (int nt = 0; nt < 8; nt++) {
                const float* p = &sK[(nt * 8 + g) * SK_ST + ks * 8 + t];
                kf[nt][0] = __float_as_uint(p[0]);
                kf[nt][1] = __float_as_uint(p[4]);
            }
#pragma unroll
            for (int nt = 0; nt < 8; nt++)
                mma8(s[nt], qf[ks], kf[nt]);
        }

        // causal mask (only the last two kv-blocks intersect the diagonal)
        if (kb >= 2 * qb) {
            int qg0 = qb * 128 + qr;
#pragma unroll
            for (int nt = 0; nt < 8; nt++) {
                int col = kb * 64 + nt * 8 + 2 * t;
                if (col     > qg0)     s[nt][0] = -1e30f;
                if (col + 1 > qg0)     s[nt][1] = -1e30f;
                if (col     > qg0 + 8) s[nt][2] = -1e30f;
                if (col + 1 > qg0 + 8) s[nt][3] = -1e30f;
            }
        }

        __syncwarp();   // this warp's prior PV reads of its P rows done

        // online softmax (exp2 domain), rows qr and qr+8
#pragma unroll
        for (int r = 0; r < 2; r++) {
            float mx = -1e30f;
#pragma unroll
            for (int nt = 0; nt < 8; nt++)
                mx = fmaxf(mx, fmaxf(s[nt][2*r], s[nt][2*r + 1]));
            mx = fmaxf(mx, __shfl_xor_sync(0xffffffffu, mx, 1));
            mx = fmaxf(mx, __shfl_xor_sync(0xffffffffu, mx, 2));
            float mnew = fmaxf(mrun[r], mx);
            float corr = ex2(mrun[r] - mnew);
            float rs = 0.f;
            float* prow = &sQP[(qr + 8 * r) * SQ_ST];
#pragma unroll
            for (int nt = 0; nt < 8; nt++) {
                float p0 = ex2(s[nt][2*r]     - mnew);
                float p1 = ex2(s[nt][2*r + 1] - mnew);
                rs += p0 + p1;
                *(float2*)&prow[nt * 8 + 2 * t] = make_float2(f2tff(p0), f2tff(p1));
            }
            rs += __shfl_xor_sync(0xffffffffu, rs, 1);
            rs += __shfl_xor_sync(0xffffffffu, rs, 2);
            lrun[r] = lrun[r] * corr + rs;
            mrun[r] = mnew;
#pragma unroll
            for (int nt = 0; nt < 8; nt++) {
                oacc[nt][2*r]     *= corr;
                oacc[nt][2*r + 1] *= corr;
            }
        }
        __syncwarp();

        // O += P V : 8 k-steps (kv=64) x 8 n-tiles (dk=64)
#pragma unroll
        for (int ks = 0; ks < 8; ks++) {
            unsigned pf[4];
            const float* pp = &sQP[qr * SQ_ST + ks * 8 + t];
            pf[0] = __float_as_uint(pp[0]);
            pf[1] = __float_as_uint(pp[8 * SQ_ST]);
            pf[2] = __float_as_uint(pp[4]);
            pf[3] = __float_as_uint(pp[8 * SQ_ST + 4]);
            unsigned vf[8][2];
#pragma unroll
            for (int nt = 0; nt < 8; nt++) {
                const float* vp = &sV[(ks * 8 + t) * SV_ST + nt * 8 + g];
                vf[nt][0] = __float_as_uint(vp[0]);
                vf[nt][1] = __float_as_uint(vp[4 * SV_ST]);
            }
#pragma unroll
            for (int nt = 0; nt < 8; nt++)
                mma8(oacc[nt], pf, vf[nt]);
        }
    }

    // epilogue: normalize, round to tf32, scatter to [B,S,D]
    const int b = bh >> 4;
    const int h = bh & 15;
#pragma unroll
    for (int r = 0; r < 2; r++) {
        float inv = 1.f / lrun[r];
        int q = qb * 128 + qr + 8 * r;
        float* dst = &g_O[((size_t)b * SSZ + q) * DSZ + h * DK];
#pragma unroll
        for (int nt = 0; nt < 8; nt++)
            *(float2*)&dst[nt * 8 + 2 * t] =
                make_float2(f2tff(oacc[nt][2*r] * inv),
                            f2tff(oacc[nt][2*r + 1] * inv));
    }
}

// ---------------------------------------------------------------------------
extern "C" void kernel_launch(void* const* d_in, const int* in_sizes, int n_in,
                              void* d_out, int out_size) {
    (void)in_sizes; (void)n_in; (void)out_size;
    const float* x  = (const float*)d_in[0];
    const float* Wq = (const float*)d_in[1];
    const float* Wk = (const float*)d_in[2];
    const float* Wv = (const float*)d_in[3];
    const float* Wo = (const float*)d_in[4];
    float* out = (float*)d_out;

    const int gemm_smem = 2 * GSTG * GBUF * (int)sizeof(float);  // 110592 B
    cudaFuncSetAttribute(gemm_qkv_kernel, cudaFuncAttributeMaxDynamicSharedMemorySize, gemm_smem);
    cudaFuncSetAttribute(gemm_out_kernel, cudaFuncAttributeMaxDynamicSharedMemorySize, gemm_smem);
    const int attn_smem = (128*SQ_ST + 2*SK_BUF + 2*SV_BUF) * (int)sizeof(float);  // 110592 B
    cudaFuncSetAttribute(attn_kernel, cudaFuncAttributeMaxDynamicSharedMemorySize, attn_smem);

    rope_table_kernel<<<(SSZ * NPAIR + 255) / 256, 256>>>();

    const int NTOT4 = NX4 + 4 * NW4;
    tf32_round_all_kernel<<<(NTOT4 + 255)/256, 256>>>(
        (const float4*)x, (const float4*)Wq, (const float4*)Wk,
        (const float4*)Wv, (const float4*)Wo);

    gemm_qkv_kernel<<<dim3(8, 32, 3), 128, gemm_smem>>>();
    attn_kernel<<<dim3(SSZ / 128, BSZ * HN), 256, attn_smem>>>();
    gemm_out_kernel<<<dim3(8, 32), 128, gemm_smem>>>(out);
}

// round 10
// speedup vs baseline: 1.0596x; 1.0596x over previous
#include <cuda_runtime.h>
#include <math.h>

#define BSZ 2
#define SSZ 2048
#define DSZ 1024
#define HN  16
#define DK  64
#define NPAIR 32

__device__ float g_Q[BSZ*HN*SSZ*DK];
__device__ float g_K[BSZ*HN*SSZ*DK];
__device__ float g_V[BSZ*HN*SSZ*DK];
__device__ float g_O[BSZ*SSZ*DSZ];
__device__ float g_X[BSZ*SSZ*DSZ];     // tf32-rounded x
__device__ float g_Wq[DSZ*DSZ];        // tf32-rounded weights
__device__ float g_Wk[DSZ*DSZ];
__device__ float g_Wv[DSZ*DSZ];
__device__ float g_Wo[DSZ*DSZ];
__device__ float g_cos[SSZ*NPAIR];
__device__ float g_sin[SSZ*NPAIR];

// ---------------------------------------------------------------------------
// helpers
// ---------------------------------------------------------------------------
__device__ __forceinline__ unsigned f2tf(float f) {
    unsigned u;
    asm("cvt.rna.tf32.f32 %0, %1;" : "=r"(u) : "f"(f));
    return u;
}
__device__ __forceinline__ float f2tff(float f) { return __uint_as_float(f2tf(f)); }

__device__ __forceinline__ float ex2(float x) {
    float y;
    asm("ex2.approx.f32 %0, %1;" : "=f"(y) : "f"(x));
    return y;
}

__device__ __forceinline__ void mma8(float* c, const unsigned* a, const unsigned* b) {
    asm volatile(
        "mma.sync.aligned.m16n8k8.row.col.f32.tf32.tf32.f32 "
        "{%0,%1,%2,%3}, {%4,%5,%6,%7}, {%8,%9}, {%0,%1,%2,%3};"
        : "+f"(c[0]), "+f"(c[1]), "+f"(c[2]), "+f"(c[3])
        : "r"(a[0]), "r"(a[1]), "r"(a[2]), "r"(a[3]), "r"(b[0]), "r"(b[1]));
}

__device__ __forceinline__ void cpa16(float* s, const float* g) {
    unsigned sa = (unsigned)__cvta_generic_to_shared(s);
    asm volatile("cp.async.cg.shared.global [%0], [%1], 16;" :: "r"(sa), "l"(g));
}
__device__ __forceinline__ void cpa_commit() {
    asm volatile("cp.async.commit_group;");
}
template <int N>
__device__ __forceinline__ void cpa_wait() {
    asm volatile("cp.async.wait_group %0;" :: "n"(N));
}

// ---------------------------------------------------------------------------
// Merged tf32 pre-round pass: x + 4 weight matrices in one launch
// ---------------------------------------------------------------------------
#define NX4 (BSZ*SSZ*DSZ/4)
#define NW4 (DSZ*DSZ/4)

__global__ void tf32_round_all_kernel(const float4* __restrict__ x,
                                      const float4* __restrict__ wq,
                                      const float4* __restrict__ wk,
                                      const float4* __restrict__ wv,
                                      const float4* __restrict__ wo) {
    int i = blockIdx.x * blockDim.x + threadIdx.x;
    const float4* src;
    float4* dst;
    if (i < NX4) {
        src = x + i;
        dst = (float4*)g_X + i;
    } else {
        int j = i - NX4;
        int wsel = j / NW4;
        int off = j - wsel * NW4;
        src = (wsel == 0 ? wq : wsel == 1 ? wk : wsel == 2 ? wv : wo) + off;
        dst = (float4*)(wsel == 0 ? g_Wq : wsel == 1 ? g_Wk : wsel == 2 ? g_Wv : g_Wo) + off;
    }
    float4 v = *src;
    float4 o;
    o.x = f2tff(v.x); o.y = f2tff(v.y); o.z = f2tff(v.z); o.w = f2tff(v.w);
    *dst = o;
}

// ---------------------------------------------------------------------------
// RoPE table
// ---------------------------------------------------------------------------
__global__ void rope_table_kernel() {
    int i = blockIdx.x * blockDim.x + threadIdx.x;
    if (i >= SSZ * NPAIR) return;
    int s = i >> 5, p = i & 31;
    double ang = (double)s * exp(-(double)p * (9.210340371976184 / 32.0));
    g_cos[i] = (float)cos(ang);
    g_sin[i] = (float)sin(ang);
}

// ---------------------------------------------------------------------------
// tf32 NT-GEMM (unchanged from R7): C[128x128] = A[128x1024] * W[128x1024]^T
// 128 thr / 4 warps in 2x2, warp tile 64x64, BK=32, 3-stage cp.async,
// fragment double-buffer across the 4 k-steps in a stage.
// ---------------------------------------------------------------------------
#define GST 36
#define GSTG 3
#define GBUF (128*GST)
#define NKT 32

struct GemmCtx { int g, t, wm, wn; };

__device__ __forceinline__ void gemm_issue(
    float* As, float* Bs, int st,
    const float* __restrict__ A, const float* __restrict__ W,
    int m0, int n0, int kb)
{
    float* as = As + st * GBUF;
    float* bs = Bs + st * GBUF;
    const int r0 = threadIdx.x >> 3;
    const int c4 = (threadIdx.x & 7) << 2;
#pragma unroll
    for (int i = 0; i < 8; i++) {
        int r = r0 + 16 * i;
        cpa16(&as[r * GST + c4], A + (size_t)(m0 + r) * 1024 + kb + c4);
        cpa16(&bs[r * GST + c4], W + (size_t)(n0 + r) * 1024 + kb + c4);
    }
}

__device__ __forceinline__ void gemm_ldfrag(
    const float* as, const float* bs, int ks,
    unsigned (&af)[4][4], unsigned (&bf)[8][2], const GemmCtx& cx)
{
    const int k0 = ks * 8;
#pragma unroll
    for (int mt = 0; mt < 4; mt++) {
        const float* p = as + (cx.wm + mt*16 + cx.g) * GST + k0 + cx.t;
        af[mt][0] = __float_as_uint(p[0]);
        af[mt][1] = __float_as_uint(p[8*GST]);
        af[mt][2] = __float_as_uint(p[4]);
        af[mt][3] = __float_as_uint(p[8*GST + 4]);
    }
#pragma unroll
    for (int nt = 0; nt < 8; nt++) {
        const float* p = bs + (cx.wn + nt*8 + cx.g) * GST + k0 + cx.t;
        bf[nt][0] = __float_as_uint(p[0]);
        bf[nt][1] = __float_as_uint(p[4]);
    }
}

__device__ __forceinline__ void gemm_main(
    const float* __restrict__ A, const float* __restrict__ W,
    int m0, int n0, float (&acc)[4][8][4],
    float* As, float* Bs, const GemmCtx& cx)
{
#pragma unroll
    for (int s = 0; s < GSTG - 1; s++) {
        gemm_issue(As, Bs, s, A, W, m0, n0, s * 32);
        cpa_commit();
    }
    unsigned af[2][4][4], bf[2][8][2];
    for (int kb = 0; kb < NKT; kb++) {
        cpa_wait<GSTG - 2>();
        __syncthreads();
        if (kb + GSTG - 1 < NKT)
            gemm_issue(As, Bs, (kb + GSTG - 1) % GSTG, A, W, m0, n0, (kb + GSTG - 1) * 32);
        cpa_commit();

        const float* as = As + (kb % GSTG) * GBUF;
        const float* bs = Bs + (kb % GSTG) * GBUF;
        gemm_ldfrag(as, bs, 0, af[0], bf[0], cx);
#pragma unroll
        for (int ks = 0; ks < 4; ks++) {
            const int cur = ks & 1;
            if (ks < 3)
                gemm_ldfrag(as, bs, ks + 1, af[cur ^ 1], bf[cur ^ 1], cx);
#pragma unroll
            for (int nt = 0; nt < 8; nt++)
#pragma unroll
                for (int mt = 0; mt < 4; mt++)
                    mma8(acc[mt][nt], af[cur][mt], bf[cur][nt]);
        }
    }
}

// QKV projection with fused RoPE, scattered to [B,H,S,dk], tf32-rounded output
__global__ __launch_bounds__(128) void gemm_qkv_kernel()
{
    extern __shared__ float sm[];
    float* As = sm;
    float* Bs = sm + GSTG * GBUF;

    const int z = blockIdx.z;
    const float* W = z == 0 ? g_Wq : (z == 1 ? g_Wk : g_Wv);
    float* dst     = z == 0 ? g_Q  : (z == 1 ? g_K  : g_V);

    const int lane = threadIdx.x & 31;
    const int wid = threadIdx.x >> 5;
    GemmCtx cx;
    cx.g = lane >> 2; cx.t = lane & 3;
    cx.wm = (wid & 1) * 64; cx.wn = (wid >> 1) * 64;
    const int m0 = blockIdx.y * 128, n0 = blockIdx.x * 128;

    float acc[4][8][4];
#pragma unroll
    for (int i = 0; i < 4; i++)
#pragma unroll
        for (int j = 0; j < 8; j++)
#pragma unroll
            for (int k = 0; k < 4; k++) acc[i][j][k] = 0.f;

    gemm_main(g_X, W, m0, n0, acc, As, Bs, cx);

    const bool do_rope = (z < 2);
#pragma unroll
    for (int mt = 0; mt < 4; mt++) {
        int m = m0 + cx.wm + mt * 16 + cx.g;
        int b = m >> 11, s = m & (SSZ - 1);
#pragma unroll
        for (int nt = 0; nt < 8; nt++) {
            int n = n0 + cx.wn + nt * 8 + 2 * cx.t;
            int h = n >> 6, c = n & 63;
            float v0 = acc[mt][nt][0], v1 = acc[mt][nt][1];
            float v2 = acc[mt][nt][2], v3 = acc[mt][nt][3];
            if (do_rope) {
                int p = c >> 1;
                float ca0 = g_cos[(s << 5) | p],       sa0 = g_sin[(s << 5) | p];
                float ca1 = g_cos[((s + 8) << 5) | p], sa1 = g_sin[((s + 8) << 5) | p];
                float r0 = v0 * ca0 - v1 * sa0;
                float r1 = v0 * sa0 + v1 * ca0;
                float r2 = v2 * ca1 - v3 * sa1;
                float r3 = v2 * sa1 + v3 * ca1;
                v0 = r0; v1 = r1; v2 = r2; v3 = r3;
            }
            v0 = f2tff(v0); v1 = f2tff(v1); v2 = f2tff(v2); v3 = f2tff(v3);
            float* base = dst + (((size_t)b * HN + h) * SSZ) * DK + c;
            *(float2*)(base + (size_t)s * DK)       = make_float2(v0, v1);
            *(float2*)(base + (size_t)(s + 8) * DK) = make_float2(v2, v3);
        }
    }
}

// Output projection: out = g_O @ g_Wo^T (both pre-rounded)
__global__ __launch_bounds__(128) void gemm_out_kernel(float* __restrict__ C)
{
    extern __shared__ float sm[];
    float* As = sm;
    float* Bs = sm + GSTG * GBUF;

    const int lane = threadIdx.x & 31;
    const int wid = threadIdx.x >> 5;
    GemmCtx cx;
    cx.g = lane >> 2; cx.t = lane & 3;
    cx.wm = (wid & 1) * 64; cx.wn = (wid >> 1) * 64;
    const int m0 = blockIdx.y * 128, n0 = blockIdx.x * 128;

    float acc[4][8][4];
#pragma unroll
    for (int i = 0; i < 4; i++)
#pragma unroll
        for (int j = 0; j < 8; j++)
#pragma unroll
            for (int k = 0; k < 4; k++) acc[i][j][k] = 0.f;

    gemm_main(g_O, g_Wo, m0, n0, acc, As, Bs, cx);

#pragma unroll
    for (int mt = 0; mt < 4; mt++) {
        int m = m0 + cx.wm + mt * 16 + cx.g;
#pragma unroll
        for (int nt = 0; nt < 8; nt++) {
            int n = n0 + cx.wn + nt * 8 + 2 * cx.t;
            *(float2*)(C + (size_t)m * 1024 + n)       = make_float2(acc[mt][nt][0], acc[mt][nt][1]);
            *(float2*)(C + (size_t)(m + 8) * 1024 + n) = make_float2(acc[mt][nt][2], acc[mt][nt][3]);
        }
    }
}

// ---------------------------------------------------------------------------
// tf32 flash attention (R7 geometry): 128 thr / 4 warps, BQ=128, BK=64.
// Warp w owns q rows w*32..w*32+31 (2 m-tiles). Q frags in registers.
// exp2-domain softmax, deferred l-reduction, whole-warp masked-block skip.
// smem: sQP[128][76] (Q tf32 then P tf32), sK[2][64][68], sV[2][64][72].
// ---------------------------------------------------------------------------
#define SQ_ST 76
#define SK_ST 68
#define SV_ST 72
#define SK_BUF (64*SK_ST)
#define SV_BUF (64*SV_ST)

__global__ __launch_bounds__(128) void attn_kernel() {
    extern __shared__ float sm[];
    float* sQP = sm;                               // 128*76
    float* sK0 = sm + 128*SQ_ST;                   // 2 x 64*68
    float* sV0 = sm + 128*SQ_ST + 2*SK_BUF;        // 2 x 64*72

    const int tid = threadIdx.x;
    const int w = tid >> 5;
    const int lane = tid & 31;
    const int g = lane >> 2, t = lane & 3;
    const int qb = (int)gridDim.x - 1 - (int)blockIdx.x;   // heavy CTAs first
    const int bh = blockIdx.y;
    const float* Qg = g_Q + (size_t)bh * SSZ * DK;
    const float* Kg = g_K + (size_t)bh * SSZ * DK;
    const float* Vg = g_V + (size_t)bh * SSZ * DK;
    const int kb_max = 2 * qb + 1;
    const int warp_row_max = qb * 128 + w * 32 + 31;   // highest q row this warp owns

    // prologue: issue K/V block 0 loads
#pragma unroll
    for (int i = 0; i < 8; i++) {
        int e = i * 128 + tid;
        int r = e >> 4, c = (e & 15) << 2;
        cpa16(&sK0[r * SK_ST + c], &Kg[(size_t)r * DK + c]);
        cpa16(&sV0[r * SV_ST + c], &Vg[(size_t)r * DK + c]);
    }
    cpa_commit();

    // stage Q: scale by (1/sqrt(dk)) * log2(e), round to tf32
    const float qscale = 0.125f * 1.4426950408889634f;
#pragma unroll
    for (int i = 0; i < 16; i++) {
        int e = i * 128 + tid;
        int r = e >> 4, c = (e & 15) << 2;
        float4 v = *(const float4*)&Qg[(size_t)(qb * 128 + r) * DK + c];
        float4 o;
        o.x = f2tff(v.x * qscale); o.y = f2tff(v.y * qscale);
        o.z = f2tff(v.z * qscale); o.w = f2tff(v.w * qscale);
        *(float4*)&sQP[r * SQ_ST + c] = o;
    }
    __syncthreads();

    // hoist Q fragments: 2 m-tiles x 8 k-steps x 4 regs
    unsigned qf[2][8][4];
#pragma unroll
    for (int mt = 0; mt < 2; mt++) {
        const int qr = w * 32 + mt * 16 + g;
#pragma unroll
        for (int ks = 0; ks < 8; ks++) {
            const float* p = &sQP[qr * SQ_ST + ks * 8 + t];
            qf[mt][ks][0] = __float_as_uint(p[0]);
            qf[mt][ks][1] = __float_as_uint(p[8 * SQ_ST]);
            qf[mt][ks][2] = __float_as_uint(p[4]);
            qf[mt][ks][3] = __float_as_uint(p[8 * SQ_ST + 4]);
        }
    }

    float mrun[2][2] = {{-1e30f, -1e30f}, {-1e30f, -1e30f}};
    float lrun[2][2] = {{0.f, 0.f}, {0.f, 0.f}};   // per-thread PARTIAL row sums
    float oacc[2][8][4];
#pragma unroll
    for (int mt = 0; mt < 2; mt++)
#pragma unroll
        for (int nt = 0; nt < 8; nt++)
#pragma unroll
            for (int k = 0; k < 4; k++) oacc[mt][nt][k] = 0.f;

    for (int kb = 0; kb <= kb_max; kb++) {
        __syncthreads();   // buffer (kb+1)&1 free; Q->qf hoist done (kb=0)
        if (kb < kb_max) {
            float* sK = sK0 + ((kb + 1) & 1) * SK_BUF;
            float* sV = sV0 + ((kb + 1) & 1) * SV_BUF;
#pragma unroll
            for (int i = 0; i < 8; i++) {
                int e = i * 128 + tid;
                int r = e >> 4, c = (e & 15) << 2;
                cpa16(&sK[r * SK_ST + c], &Kg[(size_t)((kb + 1) * 64 + r) * DK + c]);
                cpa16(&sV[r * SV_ST + c], &Vg[(size_t)((kb + 1) * 64 + r) * DK + c]);
            }
        }
        cpa_commit();
        cpa_wait<1>();
        __syncthreads();

        // whole-warp skip: this warp's entire q-tile is above the diagonal
        if (kb * 64 > warp_row_max) continue;

        const float* sK = sK0 + (kb & 1) * SK_BUF;
        const float* sV = sV0 + (kb & 1) * SV_BUF;

        // S = Q K^T : both m-tiles share each K fragment
        float s[2][8][4];
#pragma unroll
        for (int mt = 0; mt < 2; mt++)
#pragma unroll
            for (int nt = 0; nt < 8; nt++)
#pragma unroll
                for (int k = 0; k < 4; k++) s[mt][nt][k] = 0.f;

#pragma unroll
        for (int ks = 0; ks < 8; ks++) {
            unsigned kf[8][2];
#pragma unroll
            for (int nt = 0; nt < 8; nt++) {
                const float* p = &sK[(nt * 8 + g) * SK_ST + ks * 8 + t];
                kf[nt][0] = __float_as_uint(p[0]);
                kf[nt][1] = __float_as_uint(p[4]);
            }
#pragma unroll
            for (int nt = 0; nt < 8; nt++) {
                mma8(s[0][nt], qf[0][ks], kf[nt]);
                mma8(s[1][nt], qf[1][ks], kf[nt]);
            }
        }

        // causal mask (only the last two kv-blocks intersect the diagonal)
        if (kb >= 2 * qb) {
#pragma unroll
            for (int mt = 0; mt < 2; mt++) {
                int qg = qb * 128 + w * 32 + mt * 16 + g;
#pragma unroll
                for (int nt = 0; nt < 8; nt++) {
                    int col = kb * 64 + nt * 8 + 2 * t;
                    if (col     > qg)     s[mt][nt][0] = -1e30f;
                    if (col + 1 > qg)     s[mt][nt][1] = -1e30f;
                    if (col     > qg + 8) s[mt][nt][2] = -1e30f;
                    if (col + 1 > qg + 8) s[mt][nt][3] = -1e30f;
                }
            }
        }

        __syncwarp();   // this warp's prior PV reads of its P rows done

        // online softmax (exp2 domain), deferred l-reduction
#pragma unroll
        for (int mt = 0; mt < 2; mt++) {
            const int qr = w * 32 + mt * 16 + g;
#pragma unroll
            for (int r = 0; r < 2; r++) {
                float mx = -1e30f;
#pragma unroll
                for (int nt = 0; nt < 8; nt++)
                    mx = fmaxf(mx, fmaxf(s[mt][nt][2*r], s[mt][nt][2*r + 1]));
                mx = fmaxf(mx, __shfl_xor_sync(0xffffffffu, mx, 1));
                mx = fmaxf(mx, __shfl_xor_sync(0xffffffffu, mx, 2));
                float mnew = fmaxf(mrun[mt][r], mx);
                float corr = ex2(mrun[mt][r] - mnew);
                float rs = 0.f;
                float* prow = &sQP[(qr + 8 * r) * SQ_ST];
#pragma unroll
                for (int nt = 0; nt < 8; nt++) {
                    float p0 = ex2(s[mt][nt][2*r]     - mnew);
                    float p1 = ex2(s[mt][nt][2*r + 1] - mnew);
                    rs += p0 + p1;
                    *(float2*)&prow[nt * 8 + 2 * t] = make_float2(f2tff(p0), f2tff(p1));
                }
                lrun[mt][r] = lrun[mt][r] * corr + rs;   // partial: this thread's 16 cols
                mrun[mt][r] = mnew;
#pragma unroll
                for (int nt = 0; nt < 8; nt++) {
                    oacc[mt][nt][2*r]     *= corr;
                    oacc[mt][nt][2*r + 1] *= corr;
                }
            }
        }
        __syncwarp();

        // O += P V : both m-tiles share each V fragment
#pragma unroll
        for (int ks = 0; ks < 8; ks++) {
            unsigned pf[2][4];
#pragma unroll
            for (int mt = 0; mt < 2; mt++) {
                const float* pp = &sQP[(w * 32 + mt * 16 + g) * SQ_ST + ks * 8 + t];
                pf[mt][0] = __float_as_uint(pp[0]);
                pf[mt][1] = __float_as_uint(pp[8 * SQ_ST]);
                pf[mt][2] = __float_as_uint(pp[4]);
                pf[mt][3] = __float_as_uint(pp[8 * SQ_ST + 4]);
            }
            unsigned vf[8][2];
#pragma unroll
            for (int nt = 0; nt < 8; nt++) {
                const float* vp = &sV[(ks * 8 + t) * SV_ST + nt * 8 + g];
                vf[nt][0] = __float_as_uint(vp[0]);
                vf[nt][1] = __float_as_uint(vp[4 * SV_ST]);
            }
#pragma unroll
            for (int nt = 0; nt < 8; nt++) {
                mma8(oacc[0][nt], pf[0], vf[nt]);
                mma8(oacc[1][nt], pf[1], vf[nt]);
            }
        }
    }

    // epilogue: reduce deferred row sums, normalize, round, scatter to [B,S,D]
    const int b = bh >> 4;
    const int h = bh & 15;
#pragma unroll
    for (int mt = 0; mt < 2; mt++) {
#pragma unroll
        for (int r = 0; r < 2; r++) {
            float lsum = lrun[mt][r];
            lsum += __shfl_xor_sync(0xffffffffu, lsum, 1);
            lsum += __shfl_xor_sync(0xffffffffu, lsum, 2);
            float inv = 1.f / lsum;
            int q = qb * 128 + w * 32 + mt * 16 + g + 8 * r;
            float* dst = &g_O[((size_t)b * SSZ + q) * DSZ + h * DK];
#pragma unroll
            for (int nt = 0; nt < 8; nt++)
                *(float2*)&dst[nt * 8 + 2 * t] =
                    make_float2(f2tff(oacc[mt][nt][2*r] * inv),
                                f2tff(oacc[mt][nt][2*r + 1] * inv));
        }
    }
}

// ---------------------------------------------------------------------------
extern "C" void kernel_launch(void* const* d_in, const int* in_sizes, int n_in,
                              void* d_out, int out_size) {
    (void)in_sizes; (void)n_in; (void)out_size;
    const float* x  = (const float*)d_in[0];
    const float* Wq = (const float*)d_in[1];
    const float* Wk = (const float*)d_in[2];
    const float* Wv = (const float*)d_in[3];
    const float* Wo = (const float*)d_in[4];
    float* out = (float*)d_out;

    const int gemm_smem = 2 * GSTG * GBUF * (int)sizeof(float);  // 110592 B
    cudaFuncSetAttribute(gemm_qkv_kernel, cudaFuncAttributeMaxDynamicSharedMemorySize, gemm_smem);
    cudaFuncSetAttribute(gemm_out_kernel, cudaFuncAttributeMaxDynamicSharedMemorySize, gemm_smem);
    const int attn_smem = (128*SQ_ST + 2*SK_BUF + 2*SV_BUF) * (int)sizeof(float);  // 110592 B
    cudaFuncSetAttribute(attn_kernel, cudaFuncAttributeMaxDynamicSharedMemorySize, attn_smem);

    rope_table_kernel<<<(SSZ * NPAIR + 255) / 256, 256>>>();

    const int NTOT4 = NX4 + 4 * NW4;
    tf32_round_all_kernel<<<(NTOT4 + 255)/256, 256>>>(
        (const float4*)x, (const float4*)Wq, (const float4*)Wk,
        (const float4*)Wv, (const float4*)Wo);

    gemm_qkv_kernel<<<dim3(8, 32, 3), 128, gemm_smem>>>();
    attn_kernel<<<dim3(SSZ / 128, BSZ * HN), 128, attn_smem>>>();
    gemm_out_kernel<<<dim3(8, 32), 128, gemm_smem>>>(out);
}

// round 11
// speedup vs baseline: 1.7247x; 1.6276x over previous
#include <cuda_runtime.h>
#include <cuda_fp16.h>
#include <math.h>

#define BSZ 2
#define SSZ 2048
#define DSZ 1024
#define HN  16
#define DK  64
#define NPAIR 32

__device__ __half g_Q[BSZ*HN*SSZ*DK];
__device__ __half g_K[BSZ*HN*SSZ*DK];
__device__ __half g_V[BSZ*HN*SSZ*DK];   // TRANSPOSED: [B,H,dk,S]
__device__ __half g_O[BSZ*SSZ*DSZ];
__device__ __half g_X[BSZ*SSZ*DSZ];
__device__ __half g_Wq[DSZ*DSZ];
__device__ __half g_Wk[DSZ*DSZ];
__device__ __half g_Wv[DSZ*DSZ];
__device__ __half g_Wo[DSZ*DSZ];
__device__ float g_cos[SSZ*NPAIR];
__device__ float g_sin[SSZ*NPAIR];

// ---------------------------------------------------------------------------
// helpers
// ---------------------------------------------------------------------------
__device__ __forceinline__ float ex2(float x) {
    float y;
    asm("ex2.approx.f32 %0, %1;" : "=f"(y) : "f"(x));
    return y;
}

__device__ __forceinline__ void mma16(float* c, const unsigned* a, const unsigned* b) {
    asm volatile(
        "mma.sync.aligned.m16n8k16.row.col.f32.f16.f16.f32 "
        "{%0,%1,%2,%3}, {%4,%5,%6,%7}, {%8,%9}, {%0,%1,%2,%3};"
        : "+f"(c[0]), "+f"(c[1]), "+f"(c[2]), "+f"(c[3])
        : "r"(a[0]), "r"(a[1]), "r"(a[2]), "r"(a[3]), "r"(b[0]), "r"(b[1]));
}

__device__ __forceinline__ void cpa16(void* s, const void* g) {
    unsigned sa = (unsigned)__cvta_generic_to_shared(s);
    asm volatile("cp.async.cg.shared.global [%0], [%1], 16;" :: "r"(sa), "l"(g));
}
__device__ __forceinline__ void cpa_commit() {
    asm volatile("cp.async.commit_group;");
}
template <int N>
__device__ __forceinline__ void cpa_wait() {
    asm volatile("cp.async.wait_group %0;" :: "n"(N));
}

// ---------------------------------------------------------------------------
// fp32 -> fp16 cast pass: x + 4 weight matrices, 8 floats per thread
// ---------------------------------------------------------------------------
#define NX8 (BSZ*SSZ*DSZ/8)
#define NW8 (DSZ*DSZ/8)

__global__ void cast_all_kernel(const float4* __restrict__ x,
                                const float4* __restrict__ wq,
                                const float4* __restrict__ wk,
                                const float4* __restrict__ wv,
                                const float4* __restrict__ wo) {
    int i = blockIdx.x * blockDim.x + threadIdx.x;
    if (i >= NX8 + 4 * NW8) return;
    const float4* src;
    __half* dst;
    int off;
    if (i < NX8) {
        src = x; dst = g_X; off = i;
    } else {
        int j = i - NX8;
        int wsel = j / NW8;
        off = j - wsel * NW8;
        src = (wsel == 0 ? wq : wsel == 1 ? wk : wsel == 2 ? wv : wo);
        dst = (wsel == 0 ? g_Wq : wsel == 1 ? g_Wk : wsel == 2 ? g_Wv : g_Wo);
    }
    float4 a = src[2 * off], b = src[2 * off + 1];
    __half2 h0 = __floats2half2_rn(a.x, a.y);
    __half2 h1 = __floats2half2_rn(a.z, a.w);
    __half2 h2 = __floats2half2_rn(b.x, b.y);
    __half2 h3 = __floats2half2_rn(b.z, b.w);
    uint4 pack;
    pack.x = *(unsigned*)&h0; pack.y = *(unsigned*)&h1;
    pack.z = *(unsigned*)&h2; pack.w = *(unsigned*)&h3;
    *((uint4*)dst + off) = pack;
}

// ---------------------------------------------------------------------------
// RoPE table
// ---------------------------------------------------------------------------
__global__ void rope_table_kernel() {
    int i = blockIdx.x * blockDim.x + threadIdx.x;
    if (i >= SSZ * NPAIR) return;
    int s = i >> 5, p = i & 31;
    double ang = (double)s * exp(-(double)p * (9.210340371976184 / 32.0));
    g_cos[i] = (float)cos(ang);
    g_sin[i] = (float)sin(ang);
}

// ---------------------------------------------------------------------------
// fp16 NT-GEMM: C[128x128] = A[128x1024] * W[128x1024]^T
// 128 thr / 4 warps 2x2, warp tile 64x64, BK=32 halves (2 x k16), 3-stage
// cp.async. Row stride 40 halves (word 20 == 4 mod 8 -> conflict-free).
// ---------------------------------------------------------------------------
#define GST 40           // halves per smem row
#define GSTW 20          // 32-bit words per smem row
#define GSTG 3
#define GBUF (128*GST)   // halves per stage per matrix
#define NKT 32           // 1024 / 32

struct GemmCtx { int g, t, wm, wn; };

__device__ __forceinline__ void gemm_issue(
    __half* As, __half* Bs, int st,
    const __half* __restrict__ A, const __half* __restrict__ W,
    int m0, int n0, int kh)
{
    __half* as = As + st * GBUF;
    __half* bs = Bs + st * GBUF;
    const int r0 = threadIdx.x >> 2;
    const int c8 = (threadIdx.x & 3) << 3;
#pragma unroll
    for (int i = 0; i < 4; i++) {
        int r = r0 + 32 * i;
        cpa16(&as[r * GST + c8], A + (size_t)(m0 + r) * 1024 + kh + c8);
        cpa16(&bs[r * GST + c8], W + (size_t)(n0 + r) * 1024 + kh + c8);
    }
}

__device__ __forceinline__ void gemm_ldfrag(
    const __half* as, const __half* bs, int ks,
    unsigned (&af)[4][4], unsigned (&bf)[8][2], const GemmCtx& cx)
{
    const unsigned* aw = (const unsigned*)as;
    const unsigned* bw = (const unsigned*)bs;
    const int k0 = ks * 8;
#pragma unroll
    for (int mt = 0; mt < 4; mt++) {
        int base = (cx.wm + mt*16 + cx.g) * GSTW + k0 + cx.t;
        af[mt][0] = aw[base];
        af[mt][1] = aw[base + 8*GSTW];
        af[mt][2] = aw[base + 4];
        af[mt][3] = aw[base + 8*GSTW + 4];
    }
#pragma unroll
    for (int nt = 0; nt < 8; nt++) {
        int base = (cx.wn + nt*8 + cx.g) * GSTW + k0 + cx.t;
        bf[nt][0] = bw[base];
        bf[nt][1] = bw[base + 4];
    }
}

__device__ __forceinline__ void gemm_main(
    const __half* __restrict__ A, const __half* __restrict__ W,
    int m0, int n0, float (&acc)[4][8][4],
    __half* As, __half* Bs, const GemmCtx& cx)
{
#pragma unroll
    for (int s = 0; s < GSTG - 1; s++) {
        gemm_issue(As, Bs, s, A, W, m0, n0, s * 32);
        cpa_commit();
    }
    unsigned af[2][4][4], bf[2][8][2];
    for (int kb = 0; kb < NKT; kb++) {
        cpa_wait<GSTG - 2>();
        __syncthreads();
        if (kb + GSTG - 1 < NKT)
            gemm_issue(As, Bs, (kb + GSTG - 1) % GSTG, A, W, m0, n0, (kb + GSTG - 1) * 32);
        cpa_commit();

        const __half* as = As + (kb % GSTG) * GBUF;
        const __half* bs = Bs + (kb % GSTG) * GBUF;
        gemm_ldfrag(as, bs, 0, af[0], bf[0], cx);
#pragma unroll
        for (int ks = 0; ks < 2; ks++) {
            const int cur = ks & 1;
            if (ks < 1)
                gemm_ldfrag(as, bs, ks + 1, af[cur ^ 1], bf[cur ^ 1], cx);
#pragma unroll
            for (int nt = 0; nt < 8; nt++)
#pragma unroll
                for (int mt = 0; mt < 4; mt++)
                    mma16(acc[mt][nt], af[cur][mt], bf[cur][nt]);
        }
    }
}

// QKV projection: fused RoPE (Q,K), fused softmax scale (Q), V transposed.
__global__ __launch_bounds__(128) void gemm_qkv_kernel()
{
    extern __shared__ __half smh[];
    __half* As = smh;
    __half* Bs = smh + GSTG * GBUF;

    const int z = blockIdx.z;
    const __half* W = z == 0 ? g_Wq : (z == 1 ? g_Wk : g_Wv);
    __half* dst     = z == 0 ? g_Q  : (z == 1 ? g_K  : g_V);

    const int lane = threadIdx.x & 31;
    const int wid = threadIdx.x >> 5;
    GemmCtx cx;
    cx.g = lane >> 2; cx.t = lane & 3;
    cx.wm = (wid & 1) * 64; cx.wn = (wid >> 1) * 64;
    const int m0 = blockIdx.y * 128, n0 = blockIdx.x * 128;

    float acc[4][8][4];
#pragma unroll
    for (int i = 0; i < 4; i++)
#pragma unroll
        for (int j = 0; j < 8; j++)
#pragma unroll
            for (int k = 0; k < 4; k++) acc[i][j][k] = 0.f;

    gemm_main(g_X, W, m0, n0, acc, As, Bs, cx);

    const float qsc = 0.125f * 1.4426950408889634f;   // 1/sqrt(dk) * log2(e)
#pragma unroll
    for (int mt = 0; mt < 4; mt++) {
        int m = m0 + cx.wm + mt * 16 + cx.g;
        int b = m >> 11, s = m & (SSZ - 1);
#pragma unroll
        for (int nt = 0; nt < 8; nt++) {
            int n = n0 + cx.wn + nt * 8 + 2 * cx.t;
            int h = n >> 6, c = n & 63;
            float v0 = acc[mt][nt][0], v1 = acc[mt][nt][1];
            float v2 = acc[mt][nt][2], v3 = acc[mt][nt][3];
            if (z == 2) {
                // V: store transposed [B,H,dk,S]
                __half* dv = dst + (((size_t)(b * HN + h)) * DK + c) * SSZ + s;
                dv[0]       = __float2half_rn(v0);
                dv[SSZ]     = __float2half_rn(v1);
                dv[8]       = __float2half_rn(v2);
                dv[SSZ + 8] = __float2half_rn(v3);
            } else {
                int p = c >> 1;
                float ca0 = g_cos[(s << 5) | p],       sa0 = g_sin[(s << 5) | p];
                float ca1 = g_cos[((s + 8) << 5) | p], sa1 = g_sin[((s + 8) << 5) | p];
                float r0 = v0 * ca0 - v1 * sa0;
                float r1 = v0 * sa0 + v1 * ca0;
                float r2 = v2 * ca1 - v3 * sa1;
                float r3 = v2 * sa1 + v3 * ca1;
                if (z == 0) { r0 *= qsc; r1 *= qsc; r2 *= qsc; r3 *= qsc; }
                __half* base = dst + (((size_t)(b * HN + h) * SSZ)) * DK + c;
                *(__half2*)(base + (size_t)s * DK)       = __floats2half2_rn(r0, r1);
                *(__half2*)(base + (size_t)(s + 8) * DK) = __floats2half2_rn(r2, r3);
            }
        }
    }
}

// Output projection: out = g_O @ g_Wo^T, fp32 result
__global__ __launch_bounds__(128) void gemm_out_kernel(float* __restrict__ C)
{
    extern __shared__ __half smh[];
    __half* As = smh;
    __half* Bs = smh + GSTG * GBUF;

    const int lane = threadIdx.x & 31;
    const int wid = threadIdx.x >> 5;
    GemmCtx cx;
    cx.g = lane >> 2; cx.t = lane & 3;
    cx.wm = (wid & 1) * 64; cx.wn = (wid >> 1) * 64;
    const int m0 = blockIdx.y * 128, n0 = blockIdx.x * 128;

    float acc[4][8][4];
#pragma unroll
    for (int i = 0; i < 4; i++)
#pragma unroll
        for (int j = 0; j < 8; j++)
#pragma unroll
            for (int k = 0; k < 4; k++) acc[i][j][k] = 0.f;

    gemm_main(g_O, g_Wo, m0, n0, acc, As, Bs, cx);

#pragma unroll
    for (int mt = 0; mt < 4; mt++) {
        int m = m0 + cx.wm + mt * 16 + cx.g;
#pragma unroll
        for (int nt = 0; nt < 8; nt++) {
            int n = n0 + cx.wn + nt * 8 + 2 * cx.t;
            *(float2*)(C + (size_t)m * 1024 + n)       = make_float2(acc[mt][nt][0], acc[mt][nt][1]);
            *(float2*)(C + (size_t)(m + 8) * 1024 + n) = make_float2(acc[mt][nt][2], acc[mt][nt][3]);
        }
    }
}

// ---------------------------------------------------------------------------
// fp16 flash attention: 128 thr / 4 warps, BQ=128, BK=64, dk=64.
// Q frags direct from gmem (pre-scaled); V transposed in gmem.
// smem: sP[128][72], sK[2][64][72], sVt[2][64][72] halves (54 KB).
// exp2 softmax, deferred l-reduction, whole-warp masked-block skip.
// ---------------------------------------------------------------------------
#define AST 72     // halves per smem row
#define ASTW 36    // words per smem row
#define AKBUF (64*AST)

__global__ __launch_bounds__(128) void attn_kernel() {
    extern __shared__ __half smh[];
    __half* sP  = smh;                   // 128*72
    __half* sK0 = smh + 128*AST;         // 2 x 64*72
    __half* sV0 = smh + 128*AST + 2*AKBUF;

    const int tid = threadIdx.x;
    const int w = tid >> 5;
    const int lane = tid & 31;
    const int g = lane >> 2, t = lane & 3;
    const int qb = (int)gridDim.x - 1 - (int)blockIdx.x;   // heavy CTAs first
    const int bh = blockIdx.y;
    const __half* Qg  = g_Q + (size_t)bh * SSZ * DK;
    const __half* Kg  = g_K + (size_t)bh * SSZ * DK;
    const __half* Vtg = g_V + (size_t)bh * DK * SSZ;       // [dk][S]
    const int kb_max = 2 * qb + 1;
    const int warp_row_max = qb * 128 + w * 32 + 31;

    // prologue: issue K/V block 0 loads (64 rows x 64 halves each)
#pragma unroll
    for (int i = 0; i < 4; i++) {
        int e = i * 128 + tid;
        int r = e >> 3, c8 = (e & 7) << 3;
        cpa16(&sK0[r * AST + c8], Kg + (size_t)r * DK + c8);
        cpa16(&sV0[r * AST + c8], Vtg + (size_t)r * SSZ + c8);
    }
    cpa_commit();

    // Q fragments direct from gmem (already scaled by qsc, fp16)
    unsigned qf[2][4][4];
#pragma unroll
    for (int mt = 0; mt < 2; mt++) {
        int q0 = qb * 128 + w * 32 + mt * 16 + g;
#pragma unroll
        for (int ks = 0; ks < 4; ks++) {
            const __half* p = Qg + (size_t)q0 * DK + ks * 16 + 2 * t;
            qf[mt][ks][0] = *(const unsigned*)(p);
            qf[mt][ks][1] = *(const unsigned*)(p + 8 * DK);
            qf[mt][ks][2] = *(const unsigned*)(p + 8);
            qf[mt][ks][3] = *(const unsigned*)(p + 8 * DK + 8);
        }
    }

    float mrun[2][2] = {{-1e30f, -1e30f}, {-1e30f, -1e30f}};
    float lrun[2][2] = {{0.f, 0.f}, {0.f, 0.f}};
    float oacc[2][8][4];
#pragma unroll
    for (int mt = 0; mt < 2; mt++)
#pragma unroll
        for (int nt = 0; nt < 8; nt++)
#pragma unroll
            for (int k = 0; k < 4; k++) oacc[mt][nt][k] = 0.f;

    for (int kb = 0; kb <= kb_max; kb++) {
        __syncthreads();   // buffer (kb+1)&1 free
        if (kb < kb_max) {
            __half* sK = sK0 + ((kb + 1) & 1) * AKBUF;
            __half* sV = sV0 + ((kb + 1) & 1) * AKBUF;
#pragma unroll
            for (int i = 0; i < 4; i++) {
                int e = i * 128 + tid;
                int r = e >> 3, c8 = (e & 7) << 3;
                cpa16(&sK[r * AST + c8], Kg + (size_t)((kb + 1) * 64 + r) * DK + c8);
                cpa16(&sV[r * AST + c8], Vtg + (size_t)r * SSZ + (kb + 1) * 64 + c8);
            }
        }
        cpa_commit();
        cpa_wait<1>();
        __syncthreads();

        // whole-warp skip: entire q-tile above the diagonal
        if (kb * 64 > warp_row_max) continue;

        const unsigned* kw = (const unsigned*)(sK0 + (kb & 1) * AKBUF);
        const unsigned* vw = (const unsigned*)(sV0 + (kb & 1) * AKBUF);

        // S = Q K^T : 4 k16-steps over dk, 8 n-tiles over kv
        float s[2][8][4];
#pragma unroll
        for (int mt = 0; mt < 2; mt++)
#pragma unroll
            for (int nt = 0; nt < 8; nt++)
#pragma unroll
                for (int k = 0; k < 4; k++) s[mt][nt][k] = 0.f;

#pragma unroll
        for (int ks = 0; ks < 4; ks++) {
            unsigned kf[8][2];
#pragma unroll
            for (int nt = 0; nt < 8; nt++) {
                int base = (nt * 8 + g) * ASTW + ks * 8 + t;
                kf[nt][0] = kw[base];
                kf[nt][1] = kw[base + 4];
            }
#pragma unroll
            for (int nt = 0; nt < 8; nt++) {
                mma16(s[0][nt], qf[0][ks], kf[nt]);
                mma16(s[1][nt], qf[1][ks], kf[nt]);
            }
        }

        // causal mask
        if (kb >= 2 * qb) {
#pragma unroll
            for (int mt = 0; mt < 2; mt++) {
                int qg = qb * 128 + w * 32 + mt * 16 + g;
#pragma unroll
                for (int nt = 0; nt < 8; nt++) {
                    int col = kb * 64 + nt * 8 + 2 * t;
                    if (col     > qg)     s[mt][nt][0] = -1e30f;
                    if (col + 1 > qg)     s[mt][nt][1] = -1e30f;
                    if (col     > qg + 8) s[mt][nt][2] = -1e30f;
                    if (col + 1 > qg + 8) s[mt][nt][3] = -1e30f;
                }
            }
        }

        __syncwarp();   // this warp's prior PV reads of its P rows done

        // online softmax (exp2 domain), deferred l-reduction
#pragma unroll
        for (int mt = 0; mt < 2; mt++) {
            const int qr = w * 32 + mt * 16 + g;
#pragma unroll
            for (int r = 0; r < 2; r++) {
                float mx = -1e30f;
#pragma unroll
                for (int nt = 0; nt < 8; nt++)
                    mx = fmaxf(mx, fmaxf(s[mt][nt][2*r], s[mt][nt][2*r + 1]));
                mx = fmaxf(mx, __shfl_xor_sync(0xffffffffu, mx, 1));
                mx = fmaxf(mx, __shfl_xor_sync(0xffffffffu, mx, 2));
                float mnew = fmaxf(mrun[mt][r], mx);
                float corr = ex2(mrun[mt][r] - mnew);
                float rs = 0.f;
                __half* prow = sP + (qr + 8 * r) * AST;
#pragma unroll
                for (int nt = 0; nt < 8; nt++) {
                    float p0 = ex2(s[mt][nt][2*r]     - mnew);
                    float p1 = ex2(s[mt][nt][2*r + 1] - mnew);
                    rs += p0 + p1;
                    *(__half2*)(prow + nt * 8 + 2 * t) = __floats2half2_rn(p0, p1);
                }
                lrun[mt][r] = lrun[mt][r] * corr + rs;
                mrun[mt][r] = mnew;
#pragma unroll
                for (int nt = 0; nt < 8; nt++) {
                    oacc[mt][nt][2*r]     *= corr;
                    oacc[mt][nt][2*r + 1] *= corr;
                }
            }
        }
        __syncwarp();

        // O += P V : 4 k16-steps over kv, 8 n-tiles over dk (V transposed)
        const unsigned* pw = (const unsigned*)sP;
#pragma unroll
        for (int ks = 0; ks < 4; ks++) {
            unsigned pf[2][4];
#pragma unroll
            for (int mt = 0; mt < 2; mt++) {
                int base = (w * 32 + mt * 16 + g) * ASTW + ks * 8 + t;
                pf[mt][0] = pw[base];
                pf[mt][1] = pw[base + 8 * ASTW];
                pf[mt][2] = pw[base + 4];
                pf[mt][3] = pw[base + 8 * ASTW + 4];
            }
            unsigned vf[8][2];
#pragma unroll
            for (int nt = 0; nt < 8; nt++) {
                int base = (nt * 8 + g) * ASTW + ks * 8 + t;
                vf[nt][0] = vw[base];
                vf[nt][1] = vw[base + 4];
            }
#pragma unroll
            for (int nt = 0; nt < 8; nt++) {
                mma16(oacc[0][nt], pf[0], vf[nt]);
                mma16(oacc[1][nt], pf[1], vf[nt]);
            }
        }
    }

    // epilogue: reduce deferred row sums, normalize, store fp16 to [B,S,D]
    const int b = bh >> 4;
    const int h = bh & 15;
#pragma unroll
    for (int mt = 0; mt < 2; mt++) {
#pragma unroll
        for (int r = 0; r < 2; r++) {
            float lsum = lrun[mt][r];
            lsum += __shfl_xor_sync(0xffffffffu, lsum, 1);
            lsum += __shfl_xor_sync(0xffffffffu, lsum, 2);
            float inv = 1.f / lsum;
            int q = qb * 128 + w * 32 + mt * 16 + g + 8 * r;
            __half* dst = g_O + ((size_t)b * SSZ + q) * DSZ + h * DK;
#pragma unroll
            for (int nt = 0; nt < 8; nt++)
                *(__half2*)(dst + nt * 8 + 2 * t) =
                    __floats2half2_rn(oacc[mt][nt][2*r] * inv,
                                      oacc[mt][nt][2*r + 1] * inv);
        }
    }
}

// ---------------------------------------------------------------------------
extern "C" void kernel_launch(void* const* d_in, const int* in_sizes, int n_in,
                              void* d_out, int out_size) {
    (void)in_sizes; (void)n_in; (void)out_size;
    const float* x  = (const float*)d_in[0];
    const float* Wq = (const float*)d_in[1];
    const float* Wk = (const float*)d_in[2];
    const float* Wv = (const float*)d_in[3];
    const float* Wo = (const float*)d_in[4];
    float* out = (float*)d_out;

    const int gemm_smem = 2 * GSTG * GBUF * (int)sizeof(__half);   // 61440 B
    cudaFuncSetAttribute(gemm_qkv_kernel, cudaFuncAttributeMaxDynamicSharedMemorySize, gemm_smem);
    cudaFuncSetAttribute(gemm_out_kernel, cudaFuncAttributeMaxDynamicSharedMemorySize, gemm_smem);
    const int attn_smem = (128*AST + 4*AKBUF) * (int)sizeof(__half);  // 55296 B
    cudaFuncSetAttribute(attn_kernel, cudaFuncAttributeMaxDynamicSharedMemorySize, attn_smem);

    rope_table_kernel<<<(SSZ * NPAIR + 255) / 256, 256>>>();

    const int NTOT8 = NX8 + 4 * NW8;
    cast_all_kernel<<<(NTOT8 + 255)/256, 256>>>(
        (const float4*)x, (const float4*)Wq, (const float4*)Wk,
        (const float4*)Wv, (const float4*)Wo);

    gemm_qkv_kernel<<<dim3(8, 32, 3), 128, gemm_smem>>>();
    attn_kernel<<<dim3(SSZ / 128, BSZ * HN), 128, attn_smem>>>();
    gemm_out_kernel<<<dim3(8, 32), 128, gemm_smem>>>(out);
}